// round 1
// baseline (speedup 1.0000x reference)
#include <cuda_runtime.h>
#include <math.h>

#define NN      32768
#define NHOPS   6
#define NHEADS_ 8
#define NHID_   64
#define NFEAT_  512
#define NSSF_   256
#define NCLASS_ 40
#define NEG_    0.2f
#define COS_EPS_ 1e-6f

// output layout (flattened tuple, element offsets)
#define OUT_OFF   0
#define SSFN_OFF  (NN*NCLASS_)                    // 1310720
#define Z_OFF     (SSFN_OFF + NSSF_*NCLASS_)      // 1320960
#define LOSS_OFF  (Z_OFF + NN*NSSF_)              // 9709568
#define SIGMA_OFF (LOSS_OFF + NN*NCLASS_)         // 11020288

// scratch (static device globals — no runtime allocation)
__device__ float g_z1[(long)NN * 512];   // attention output [N, heads*hid]
__device__ float g_zsq[NN];
__device__ float g_zn[NN];
__device__ float g_csq[NCLASS_];
__device__ float g_cn[NCLASS_];

// ---------------------------------------------------------------------------
// K0: exact sparsify threshold (5121-st smallest of |ssf|, via bit-pattern
// binary search), ssf_norm, per-class column norms, sigma copy. One block.
// ---------------------------------------------------------------------------
__global__ void __launch_bounds__(256) smn_k0_ssf(
    const float* __restrict__ ssf, const float* __restrict__ sigma,
    float* __restrict__ dout)
{
    __shared__ float fbuf[NSSF_ * NCLASS_];   // 40 KB, reused: keys -> ssfn
    __shared__ int   cnt_s[256];
    unsigned* keys = reinterpret_cast<unsigned*>(fbuf);
    const int tid = threadIdx.x;

    for (int i = tid; i < NSSF_ * NCLASS_; i += 256)
        keys[i] = __float_as_uint(fabsf(ssf[i]));
    __syncthreads();

    // smallest key K with count(keys <= K) >= 5121  => exact flat_sorted[5120]
    unsigned lo = 0u, hi = 0x7f800000u;
    while (lo < hi) {
        unsigned mid = (lo + hi) >> 1;
        int c = 0;
        for (int i = tid; i < NSSF_ * NCLASS_; i += 256) c += (keys[i] <= mid);
        cnt_s[tid] = c;
        __syncthreads();
        for (int s = 128; s > 0; s >>= 1) {
            if (tid < s) cnt_s[tid] += cnt_s[tid + s];
            __syncthreads();
        }
        int total = cnt_s[0];
        __syncthreads();
        if (total >= 5121) hi = mid; else lo = mid + 1;
    }
    const float thr = __uint_as_float(lo);

    // one thread per ssf row (256 rows, 40 cols)
    float row[NCLASS_];
    float rs = 0.f;
    const float* srow = ssf + tid * NCLASS_;
#pragma unroll
    for (int j = 0; j < NCLASS_; j++) {
        float v = srow[j];
        v = (fabsf(v) >= thr) ? v : 0.f;
        row[j] = v;
        rs += fabsf(v);
    }
    const float inv = 1.f / fmaxf(rs, 1e-12f);
#pragma unroll
    for (int j = 0; j < NCLASS_; j++) {
        float v = row[j] * inv;
        dout[SSFN_OFF + tid * NCLASS_ + j] = v;
        fbuf[tid * NCLASS_ + j] = v;     // keep for column-norm pass
    }
    __syncthreads();

    if (tid < NCLASS_) {
        float c2 = 0.f;
        for (int i = 0; i < NSSF_; i++) {
            float v = fbuf[i * NCLASS_ + tid];
            c2 += v * v;
        }
        g_csq[tid] = c2;
        g_cn[tid]  = fmaxf(sqrtf(c2), COS_EPS_);
    }
    if (tid < 2) dout[SIGMA_OFF + tid] = sigma[tid];
}

// ---------------------------------------------------------------------------
// K1: fused  h = lrelu(x @ W_pre^T + b)  ->  hop-attention softmax  ->  z1.
// Block tile: 16 nodes (=96 GEMM rows) x 64 cols (one head). Each thread owns
// all 6 hops of one node x 4 cols, so softmax over hops is thread-local.
// grid = (8 heads, 2048 node tiles); adjacent blocks share the A tile (L2).
// ---------------------------------------------------------------------------
__global__ void __launch_bounds__(256) smn_k1_pre_att(
    const float* __restrict__ x, const float* __restrict__ Wp,
    const float* __restrict__ bp, const float* __restrict__ att)
{
    __shared__ float As[96][33];        // x tile, [row][k]
    __shared__ float Bs[32][68];        // W_pre tile, [k][col]
    __shared__ float atts[NHOPS][64];   // att slice for this head

    const int tid  = threadIdx.x;
    const int head = blockIdx.x;
    const int node0 = blockIdx.y * 16;
    const int col0  = head * 64;

    if (tid < 192) {
        int i0 = tid;        atts[i0 / 64][i0 % 64] = att[head * 384 + i0];
        int i1 = tid + 192;  atts[i1 / 64][i1 % 64] = att[head * 384 + i1];
    }

    float acc[NHOPS][4];
#pragma unroll
    for (int r = 0; r < NHOPS; r++)
#pragma unroll
        for (int c = 0; c < 4; c++) acc[r][c] = 0.f;

    const int tx = tid & 15;       // 16 col groups of 4
    const int ty = tid >> 4;       // 16 nodes
    const int kk = tid & 31;
    const int rb = tid >> 5;       // 0..7
    const long row0 = (long)node0 * NHOPS;

    for (int k0 = 0; k0 < NFEAT_; k0 += 32) {
#pragma unroll
        for (int p = 0; p < 12; p++)
            As[rb + p * 8][kk] = x[(row0 + rb + p * 8) * NFEAT_ + k0 + kk];
#pragma unroll
        for (int p = 0; p < 8; p++)
            Bs[kk][rb + p * 8] = Wp[(long)(col0 + rb + p * 8) * NFEAT_ + k0 + kk];
        __syncthreads();
#pragma unroll
        for (int k = 0; k < 32; k++) {
            float4 b = *(const float4*)&Bs[k][tx * 4];
#pragma unroll
            for (int r = 0; r < NHOPS; r++) {
                float a = As[ty * NHOPS + r][k];
                acc[r][0] += a * b.x;
                acc[r][1] += a * b.y;
                acc[r][2] += a * b.z;
                acc[r][3] += a * b.w;
            }
        }
        __syncthreads();
    }

    // epilogue: bias + lrelu + hop attention softmax
    const int node = node0 + ty;
    float4 bias4 = *(const float4*)&bp[col0 + tx * 4];
    float bv[4] = {bias4.x, bias4.y, bias4.z, bias4.w};
    float zr[4];
#pragma unroll
    for (int c = 0; c < 4; c++) {
        float h[NHOPS], am[NHOPS];
        const int hl = tx * 4 + c;
#pragma unroll
        for (int r = 0; r < NHOPS; r++) {
            float t = acc[r][c] + bv[c];
            t = t > 0.f ? t : NEG_ * t;
            h[r]  = t;
            am[r] = t * atts[r][hl];
        }
        float m = -1e30f;
        float s[NHOPS];
#pragma unroll
        for (int r = 0; r < NHOPS; r++) {
            float t = am[0] + am[r];
            t = t > 0.f ? t : NEG_ * t;
            s[r] = t;
            m = fmaxf(m, t);
        }
        float den = 0.f, num = 0.f;
#pragma unroll
        for (int r = 0; r < NHOPS; r++) {
            float w = expf(s[r] - m);
            den += w;
            num += h[r] * w;
        }
        zr[c] = num / den;
    }
    *(float4*)&g_z1[(long)node * 512 + col0 + tx * 4] =
        make_float4(zr[0], zr[1], zr[2], zr[3]);
}

// ---------------------------------------------------------------------------
// K2: z = lrelu(z1 @ W_post^T + b_post)  [N,256]; also deterministic per-row
// sum-of-squares + norm. Block tile: 32 rows x all 256 cols.
// ---------------------------------------------------------------------------
__global__ void __launch_bounds__(256) smn_k2_post(
    const float* __restrict__ Wq, const float* __restrict__ bq,
    float* __restrict__ dout)
{
    __shared__ float As[32][33];
    __shared__ float Bs[32][260];
    __shared__ float part[32][65];   // per-(row,txgroup) partial sum of squares

    const int tid  = threadIdx.x;
    const int row0 = blockIdx.x * 32;
    const int tx = tid & 63;     // 64 col groups of 4
    const int ty = tid >> 6;     // 4 row groups of 8
    const int kk = tid & 31;
    const int rb = tid >> 5;     // 0..7

    float acc[8][4];
#pragma unroll
    for (int r = 0; r < 8; r++)
#pragma unroll
        for (int c = 0; c < 4; c++) acc[r][c] = 0.f;

    for (int k0 = 0; k0 < 512; k0 += 32) {
#pragma unroll
        for (int p = 0; p < 4; p++)
            As[rb + p * 8][kk] = g_z1[(long)(row0 + rb + p * 8) * 512 + k0 + kk];
#pragma unroll
        for (int p = 0; p < 32; p++)
            Bs[kk][rb + p * 8] = Wq[(long)(rb + p * 8) * 512 + k0 + kk];
        __syncthreads();
#pragma unroll
        for (int k = 0; k < 32; k++) {
            float4 b = *(const float4*)&Bs[k][tx * 4];
#pragma unroll
            for (int r = 0; r < 8; r++) {
                float a = As[ty * 8 + r][k];
                acc[r][0] += a * b.x;
                acc[r][1] += a * b.y;
                acc[r][2] += a * b.z;
                acc[r][3] += a * b.w;
            }
        }
        __syncthreads();
    }

    float4 bias4 = *(const float4*)&bq[tx * 4];
    float bv[4] = {bias4.x, bias4.y, bias4.z, bias4.w};
#pragma unroll
    for (int r = 0; r < 8; r++) {
        const int rloc = ty * 8 + r;
        const long row = row0 + rloc;
        float v[4], sq = 0.f;
#pragma unroll
        for (int c = 0; c < 4; c++) {
            float t = acc[r][c] + bv[c];
            t = t > 0.f ? t : NEG_ * t;
            v[c] = t;
            sq += t * t;
        }
        *(float4*)&dout[Z_OFF + row * 256 + tx * 4] =
            make_float4(v[0], v[1], v[2], v[3]);
        part[rloc][tx] = sq;
    }
    __syncthreads();
    if (tid < 32) {           // deterministic per-row reduction
        float s = 0.f;
        for (int i = 0; i < 64; i++) s += part[tid][i];
        const int row = row0 + tid;
        g_zsq[row] = s;
        g_zn[row]  = fmaxf(sqrtf(s), COS_EPS_);
    }
}

// ---------------------------------------------------------------------------
// K3: out = z @ ssf_norm; spatial_dist / spatial_sim; two row log-softmaxes.
// One warp per row; lane l owns class l (and class 32+l for l<8).
// ---------------------------------------------------------------------------
__global__ void __launch_bounds__(256) smn_k3_final(float* __restrict__ dout)
{
    __shared__ float ssfn_s[NSSF_ * NCLASS_];   // 40 KB
    const float* ssfn_g = dout + SSFN_OFF;
    const int tid = threadIdx.x;
    for (int i = tid; i < NSSF_ * NCLASS_; i += 256) ssfn_s[i] = ssfn_g[i];
    __syncthreads();

    const int warp = tid >> 5, lane = tid & 31;
    const bool has2 = lane < 8;
    const int j1 = lane, j2 = 32 + lane;
    const float csq1 = g_csq[j1], cn1 = g_cn[j1];
    const float csq2 = has2 ? g_csq[j2] : 0.f;
    const float cn2  = has2 ? g_cn[j2]  : 1.f;
    const float* zbase = dout + Z_OFF;

    for (int it = 0; it < 8; it++) {
        const long row = (long)blockIdx.x * 64 + warp * 8 + it;
        const float* zr = zbase + row * 256 + lane * 8;
        float4 za = *(const float4*)zr;
        float4 zb = *(const float4*)(zr + 4);
        float zreg[8] = {za.x, za.y, za.z, za.w, zb.x, zb.y, zb.z, zb.w};

        float acc1 = 0.f, acc2 = 0.f;
#pragma unroll
        for (int m = 0; m < 8; m++) {
#pragma unroll 8
            for (int src = 0; src < 32; src++) {
                float zv = __shfl_sync(0xffffffffu, zreg[m], src);
                int i = src * 8 + m;
                acc1 += zv * ssfn_s[i * NCLASS_ + j1];
                if (has2) acc2 += zv * ssfn_s[i * NCLASS_ + j2];
            }
        }

        const float zsq = g_zsq[row];
        const float zn  = g_zn[row];
        float d1 = -sqrtf(fmaxf(zsq + csq1 - 2.f * acc1, 0.f));
        float s1 = acc1 / (zn * cn1);
        float d2 = has2 ? -sqrtf(fmaxf(zsq + csq2 - 2.f * acc2, 0.f)) : -1e30f;
        float s2 = has2 ? acc2 / (zn * cn2) : -1e30f;

        // warp max over the 40 values (d) and (s)
        float md = fmaxf(d1, d2);
        float ms = fmaxf(s1, s2);
#pragma unroll
        for (int o = 16; o > 0; o >>= 1) {
            md = fmaxf(md, __shfl_xor_sync(0xffffffffu, md, o));
            ms = fmaxf(ms, __shfl_xor_sync(0xffffffffu, ms, o));
        }
        float ed = expf(d1 - md) + (has2 ? expf(d2 - md) : 0.f);
        float es = expf(s1 - ms) + (has2 ? expf(s2 - ms) : 0.f);
#pragma unroll
        for (int o = 16; o > 0; o >>= 1) {
            ed += __shfl_xor_sync(0xffffffffu, ed, o);
            es += __shfl_xor_sync(0xffffffffu, es, o);
        }
        const float lse_d = md + logf(ed);
        const float lse_s = ms + logf(es);

        dout[OUT_OFF  + row * NCLASS_ + j1] = acc1;
        dout[LOSS_OFF + row * NCLASS_ + j1] =
            0.5f * ((d1 - lse_d) + (s1 - lse_s));
        if (has2) {
            dout[OUT_OFF  + row * NCLASS_ + j2] = acc2;
            dout[LOSS_OFF + row * NCLASS_ + j2] =
                0.5f * ((d2 - lse_d) + (s2 - lse_s));
        }
    }
}

// ---------------------------------------------------------------------------
extern "C" void kernel_launch(void* const* d_in, const int* in_sizes, int n_in,
                              void* d_out, int out_size)
{
    const float* x      = (const float*)d_in[0];
    const float* W_pre  = (const float*)d_in[1];
    const float* b_pre  = (const float*)d_in[2];
    const float* att    = (const float*)d_in[3];
    const float* W_post = (const float*)d_in[4];
    const float* b_post = (const float*)d_in[5];
    const float* ssf    = (const float*)d_in[6];
    const float* sigma  = (const float*)d_in[7];
    float* dout = (float*)d_out;

    smn_k0_ssf<<<1, 256>>>(ssf, sigma, dout);
    smn_k1_pre_att<<<dim3(NHEADS_, NN / 16), 256>>>(x, W_pre, b_pre, att);
    smn_k2_post<<<NN / 32, 256>>>(W_post, b_post, dout);
    smn_k3_final<<<NN / 64, 256>>>(dout);
}

// round 2
// speedup vs baseline: 2.2403x; 2.2403x over previous
#include <cuda_runtime.h>
#include <math.h>
#include <stdint.h>

#define NN      32768
#define NHOPS   6
#define NHEADS_ 8
#define NHID_   64
#define NFEAT_  512
#define NSSF_   256
#define NCLASS_ 40
#define NEG_    0.2f
#define COS_EPS_ 1e-6f

// output layout (flattened tuple, element offsets)
#define OUT_OFF   0
#define SSFN_OFF  (NN*NCLASS_)                    // 1310720
#define Z_OFF     (SSFN_OFF + NSSF_*NCLASS_)      // 1320960
#define LOSS_OFF  (Z_OFF + NN*NSSF_)              // 9709568
#define SIGMA_OFF (LOSS_OFF + NN*NCLASS_)         // 11020288

// scratch (static device globals — no runtime allocation)
__device__ float g_z1[(long)NN * 512];   // attention output [N, heads*hid]
__device__ float g_zsq[NN];
__device__ float g_zn[NN];
__device__ float g_csq[NCLASS_];
__device__ float g_cn[NCLASS_];

// ---------------------------------------------------------------------------
// helpers: tf32 convert (round-to-nearest) + m16n8k8 tf32 mma
// ---------------------------------------------------------------------------
__device__ __forceinline__ uint32_t f2tf(float x) {
    uint32_t y;
    asm("cvt.rna.tf32.f32 %0, %1;" : "=r"(y) : "f"(x));
    return y;
}
__device__ __forceinline__ void mma8(float c[4], const uint32_t a[4],
                                     const uint32_t b[2]) {
    asm volatile(
        "mma.sync.aligned.m16n8k8.row.col.f32.tf32.tf32.f32 "
        "{%0,%1,%2,%3}, {%4,%5,%6,%7}, {%8,%9}, {%0,%1,%2,%3};\n"
        : "+f"(c[0]), "+f"(c[1]), "+f"(c[2]), "+f"(c[3])
        : "r"(a[0]), "r"(a[1]), "r"(a[2]), "r"(a[3]), "r"(b[0]), "r"(b[1]));
}

// ---------------------------------------------------------------------------
// K0: exact sparsify threshold (5121-st smallest of |ssf|, via bit-pattern
// binary search), ssf_norm, per-class column norms, sigma copy. One block.
// ---------------------------------------------------------------------------
__global__ void __launch_bounds__(256) smn_k0_ssf(
    const float* __restrict__ ssf, const float* __restrict__ sigma,
    float* __restrict__ dout)
{
    __shared__ float fbuf[NSSF_ * NCLASS_];   // 40 KB, reused: keys -> ssfn
    __shared__ int   cnt_s[256];
    unsigned* keys = reinterpret_cast<unsigned*>(fbuf);
    const int tid = threadIdx.x;

    for (int i = tid; i < NSSF_ * NCLASS_; i += 256)
        keys[i] = __float_as_uint(fabsf(ssf[i]));
    __syncthreads();

    unsigned lo = 0u, hi = 0x7f800000u;
    while (lo < hi) {
        unsigned mid = (lo + hi) >> 1;
        int c = 0;
        for (int i = tid; i < NSSF_ * NCLASS_; i += 256) c += (keys[i] <= mid);
        cnt_s[tid] = c;
        __syncthreads();
        for (int s = 128; s > 0; s >>= 1) {
            if (tid < s) cnt_s[tid] += cnt_s[tid + s];
            __syncthreads();
        }
        int total = cnt_s[0];
        __syncthreads();
        if (total >= 5121) hi = mid; else lo = mid + 1;
    }
    const float thr = __uint_as_float(lo);

    float row[NCLASS_];
    float rs = 0.f;
    const float* srow = ssf + tid * NCLASS_;
#pragma unroll
    for (int j = 0; j < NCLASS_; j++) {
        float v = srow[j];
        v = (fabsf(v) >= thr) ? v : 0.f;
        row[j] = v;
        rs += fabsf(v);
    }
    const float inv = 1.f / fmaxf(rs, 1e-12f);
#pragma unroll
    for (int j = 0; j < NCLASS_; j++) {
        float v = row[j] * inv;
        dout[SSFN_OFF + tid * NCLASS_ + j] = v;
        fbuf[tid * NCLASS_ + j] = v;
    }
    __syncthreads();

    if (tid < NCLASS_) {
        float c2 = 0.f;
        for (int i = 0; i < NSSF_; i++) {
            float v = fbuf[i * NCLASS_ + tid];
            c2 += v * v;
        }
        g_csq[tid] = c2;
        g_cn[tid]  = fmaxf(sqrtf(c2), COS_EPS_);
    }
    if (tid < 2) dout[SIGMA_OFF + tid] = sigma[tid];
}

// ---------------------------------------------------------------------------
// K1 (tf32 tensor cores): h = lrelu(x @ W_pre^T + b) -> hop softmax -> z1.
// Block tile: 96 rows (16 nodes x 6 hops) x 128 cols (2 heads). 8 warps,
// warp tile 48x32 via m16n8k8 tf32 mma. Epilogue re-groups hops through a
// smem tile (two 64-col halves to stay under 48KB static smem).
// ---------------------------------------------------------------------------
__global__ void __launch_bounds__(256) smn_k1_tc(
    const float* __restrict__ x, const float* __restrict__ Wp,
    const float* __restrict__ bp, const float* __restrict__ att)
{
    __shared__ uint32_t sAB[8064];   // As [96][36] @0, Bs [128][36] @3456
    __shared__ float atts[768];      // att for this block's 2 heads

    const int tid  = threadIdx.x;
    const int lane = tid & 31, warp = tid >> 5;
    const int warpM = warp >> 2, warpN = warp & 3;
    const int g = lane >> 2, t = lane & 3;
    const int node0 = blockIdx.y * 16;
    const int col0  = blockIdx.x * 128;
    const long row0 = (long)node0 * NHOPS;

    for (int i = tid; i < 768; i += 256)
        atts[i] = att[2 * blockIdx.x * 384 + i];

    float acc[3][4][4];
#pragma unroll
    for (int mf = 0; mf < 3; mf++)
#pragma unroll
        for (int nf = 0; nf < 4; nf++)
#pragma unroll
            for (int v = 0; v < 4; v++) acc[mf][nf][v] = 0.f;

    for (int ks = 0; ks < NFEAT_; ks += 32) {
        // stage A (x tile): 96 rows x 32 k, float4 loads + tf32 convert
#pragma unroll
        for (int i = 0; i < 3; i++) {
            int idx = tid + i * 256;            // 0..767
            int r = idx >> 3, c4 = (idx & 7) * 4;
            float4 v = *(const float4*)(x + (row0 + r) * NFEAT_ + ks + c4);
            uint32_t* d = &sAB[r * 36 + c4];
            d[0] = f2tf(v.x); d[1] = f2tf(v.y);
            d[2] = f2tf(v.z); d[3] = f2tf(v.w);
        }
        // stage B (W_pre tile): 128 rows x 32 k
#pragma unroll
        for (int i = 0; i < 4; i++) {
            int idx = tid + i * 256;            // 0..1023
            int n = idx >> 3, c4 = (idx & 7) * 4;
            float4 v = *(const float4*)(Wp + (long)(col0 + n) * NFEAT_ + ks + c4);
            uint32_t* d = &sAB[3456 + n * 36 + c4];
            d[0] = f2tf(v.x); d[1] = f2tf(v.y);
            d[2] = f2tf(v.z); d[3] = f2tf(v.w);
        }
        __syncthreads();

#pragma unroll
        for (int kk = 0; kk < 4; kk++) {
            const int k8 = kk * 8;
            uint32_t af[3][4], bf[4][2];
#pragma unroll
            for (int mf = 0; mf < 3; mf++) {
                const int rb = warpM * 48 + mf * 16;
                af[mf][0] = sAB[(rb + g)     * 36 + k8 + t];
                af[mf][1] = sAB[(rb + g + 8) * 36 + k8 + t];
                af[mf][2] = sAB[(rb + g)     * 36 + k8 + t + 4];
                af[mf][3] = sAB[(rb + g + 8) * 36 + k8 + t + 4];
            }
#pragma unroll
            for (int nf = 0; nf < 4; nf++) {
                const int nb = warpN * 32 + nf * 8;
                bf[nf][0] = sAB[3456 + (nb + g) * 36 + k8 + t];
                bf[nf][1] = sAB[3456 + (nb + g) * 36 + k8 + t + 4];
            }
#pragma unroll
            for (int mf = 0; mf < 3; mf++)
#pragma unroll
                for (int nf = 0; nf < 4; nf++)
                    mma8(acc[mf][nf], af[mf], bf[nf]);
        }
        __syncthreads();
    }

    // epilogue: two 64-col halves through smem (Cs [96][68] reuses sAB)
    float* Cs = (float*)sAB;
#pragma unroll
    for (int half = 0; half < 2; half++) {
        if ((warpN >> 1) == half) {
#pragma unroll
            for (int mf = 0; mf < 3; mf++)
#pragma unroll
                for (int nf = 0; nf < 4; nf++) {
                    const int r  = warpM * 48 + mf * 16 + g;
                    const int cc = (warpN & 1) * 32 + nf * 8 + t * 2;
                    Cs[r * 68 + cc]           = acc[mf][nf][0];
                    Cs[r * 68 + cc + 1]       = acc[mf][nf][1];
                    Cs[(r + 8) * 68 + cc]     = acc[mf][nf][2];
                    Cs[(r + 8) * 68 + cc + 1] = acc[mf][nf][3];
                }
        }
        __syncthreads();
        {
            const int ty = tid >> 4, tx = tid & 15;
            const int node = node0 + ty;
            const int cg = half * 64 + tx * 4;       // col within 128
            float4 b4 = *(const float4*)(bp + col0 + cg);
            float bv[4] = {b4.x, b4.y, b4.z, b4.w};
            float zr[4];
#pragma unroll
            for (int c = 0; c < 4; c++) {
                float h[NHOPS], am[NHOPS], s[NHOPS];
#pragma unroll
                for (int r = 0; r < NHOPS; r++) {
                    float v = Cs[(ty * 6 + r) * 68 + tx * 4 + c] + bv[c];
                    v = v > 0.f ? v : NEG_ * v;
                    h[r]  = v;
                    am[r] = v * atts[half * 384 + r * 64 + tx * 4 + c];
                }
                float m = -1e30f;
#pragma unroll
                for (int r = 0; r < NHOPS; r++) {
                    float u = am[0] + am[r];
                    u = u > 0.f ? u : NEG_ * u;
                    s[r] = u;
                    m = fmaxf(m, u);
                }
                float den = 0.f, num = 0.f;
#pragma unroll
                for (int r = 0; r < NHOPS; r++) {
                    float w = expf(s[r] - m);
                    den += w;
                    num += h[r] * w;
                }
                zr[c] = num / den;
            }
            *(float4*)&g_z1[(long)node * 512 + col0 + cg] =
                make_float4(zr[0], zr[1], zr[2], zr[3]);
        }
        __syncthreads();
    }
}

// ---------------------------------------------------------------------------
// K2: z = lrelu(z1 @ W_post^T + b_post) [N,256] (exact fp32 SIMT), plus
// deterministic per-row sum-of-squares + norm. Block: 32 rows x 256 cols.
// ---------------------------------------------------------------------------
__global__ void __launch_bounds__(256) smn_k2_post(
    const float* __restrict__ Wq, const float* __restrict__ bq,
    float* __restrict__ dout)
{
    __shared__ float As[32][33];
    __shared__ float Bs[32][260];
    __shared__ float part[32][65];

    const int tid  = threadIdx.x;
    const int row0 = blockIdx.x * 32;
    const int tx = tid & 63;
    const int ty = tid >> 6;
    const int kk = tid & 31;
    const int rb = tid >> 5;

    float acc[8][4];
#pragma unroll
    for (int r = 0; r < 8; r++)
#pragma unroll
        for (int c = 0; c < 4; c++) acc[r][c] = 0.f;

    for (int k0 = 0; k0 < 512; k0 += 32) {
#pragma unroll
        for (int p = 0; p < 4; p++)
            As[rb + p * 8][kk] = g_z1[(long)(row0 + rb + p * 8) * 512 + k0 + kk];
#pragma unroll
        for (int p = 0; p < 32; p++)
            Bs[kk][rb + p * 8] = Wq[(long)(rb + p * 8) * 512 + k0 + kk];
        __syncthreads();
#pragma unroll
        for (int k = 0; k < 32; k++) {
            float4 b = *(const float4*)&Bs[k][tx * 4];
#pragma unroll
            for (int r = 0; r < 8; r++) {
                float a = As[ty * 8 + r][k];
                acc[r][0] += a * b.x;
                acc[r][1] += a * b.y;
                acc[r][2] += a * b.z;
                acc[r][3] += a * b.w;
            }
        }
        __syncthreads();
    }

    float4 bias4 = *(const float4*)&bq[tx * 4];
    float bv[4] = {bias4.x, bias4.y, bias4.z, bias4.w};
#pragma unroll
    for (int r = 0; r < 8; r++) {
        const int rloc = ty * 8 + r;
        const long row = row0 + rloc;
        float v[4], sq = 0.f;
#pragma unroll
        for (int c = 0; c < 4; c++) {
            float t = acc[r][c] + bv[c];
            t = t > 0.f ? t : NEG_ * t;
            v[c] = t;
            sq += t * t;
        }
        *(float4*)&dout[Z_OFF + row * 256 + tx * 4] =
            make_float4(v[0], v[1], v[2], v[3]);
        part[rloc][tx] = sq;
    }
    __syncthreads();
    if (tid < 32) {
        float s = 0.f;
        for (int i = 0; i < 64; i++) s += part[tid][i];
        const int row = row0 + tid;
        g_zsq[row] = s;
        g_zn[row]  = fmaxf(sqrtf(s), COS_EPS_);
    }
}

// ---------------------------------------------------------------------------
// K3: out = z @ ssf_norm; spatial_dist / spatial_sim; two row log-softmaxes.
// ---------------------------------------------------------------------------
__global__ void __launch_bounds__(256) smn_k3_final(float* __restrict__ dout)
{
    __shared__ float ssfn_s[NSSF_ * NCLASS_];
    const float* ssfn_g = dout + SSFN_OFF;
    const int tid = threadIdx.x;
    for (int i = tid; i < NSSF_ * NCLASS_; i += 256) ssfn_s[i] = ssfn_g[i];
    __syncthreads();

    const int warp = tid >> 5, lane = tid & 31;
    const bool has2 = lane < 8;
    const int j1 = lane, j2 = 32 + lane;
    const float csq1 = g_csq[j1], cn1 = g_cn[j1];
    const float csq2 = has2 ? g_csq[j2] : 0.f;
    const float cn2  = has2 ? g_cn[j2]  : 1.f;
    const float* zbase = dout + Z_OFF;

    for (int it = 0; it < 8; it++) {
        const long row = (long)blockIdx.x * 64 + warp * 8 + it;
        const float* zr = zbase + row * 256 + lane * 8;
        float4 za = *(const float4*)zr;
        float4 zb = *(const float4*)(zr + 4);
        float zreg[8] = {za.x, za.y, za.z, za.w, zb.x, zb.y, zb.z, zb.w};

        float acc1 = 0.f, acc2 = 0.f;
#pragma unroll
        for (int m = 0; m < 8; m++) {
#pragma unroll 8
            for (int src = 0; src < 32; src++) {
                float zv = __shfl_sync(0xffffffffu, zreg[m], src);
                int i = src * 8 + m;
                acc1 += zv * ssfn_s[i * NCLASS_ + j1];
                if (has2) acc2 += zv * ssfn_s[i * NCLASS_ + j2];
            }
        }

        const float zsq = g_zsq[row];
        const float zn  = g_zn[row];
        float d1 = -sqrtf(fmaxf(zsq + csq1 - 2.f * acc1, 0.f));
        float s1 = acc1 / (zn * cn1);
        float d2 = has2 ? -sqrtf(fmaxf(zsq + csq2 - 2.f * acc2, 0.f)) : -1e30f;
        float s2 = has2 ? acc2 / (zn * cn2) : -1e30f;

        float md = fmaxf(d1, d2);
        float ms = fmaxf(s1, s2);
#pragma unroll
        for (int o = 16; o > 0; o >>= 1) {
            md = fmaxf(md, __shfl_xor_sync(0xffffffffu, md, o));
            ms = fmaxf(ms, __shfl_xor_sync(0xffffffffu, ms, o));
        }
        float ed = expf(d1 - md) + (has2 ? expf(d2 - md) : 0.f);
        float es = expf(s1 - ms) + (has2 ? expf(s2 - ms) : 0.f);
#pragma unroll
        for (int o = 16; o > 0; o >>= 1) {
            ed += __shfl_xor_sync(0xffffffffu, ed, o);
            es += __shfl_xor_sync(0xffffffffu, es, o);
        }
        const float lse_d = md + logf(ed);
        const float lse_s = ms + logf(es);

        dout[OUT_OFF  + row * NCLASS_ + j1] = acc1;
        dout[LOSS_OFF + row * NCLASS_ + j1] =
            0.5f * ((d1 - lse_d) + (s1 - lse_s));
        if (has2) {
            dout[OUT_OFF  + row * NCLASS_ + j2] = acc2;
            dout[LOSS_OFF + row * NCLASS_ + j2] =
                0.5f * ((d2 - lse_d) + (s2 - lse_s));
        }
    }
}

// ---------------------------------------------------------------------------
extern "C" void kernel_launch(void* const* d_in, const int* in_sizes, int n_in,
                              void* d_out, int out_size)
{
    const float* x      = (const float*)d_in[0];
    const float* W_pre  = (const float*)d_in[1];
    const float* b_pre  = (const float*)d_in[2];
    const float* att    = (const float*)d_in[3];
    const float* W_post = (const float*)d_in[4];
    const float* b_post = (const float*)d_in[5];
    const float* ssf    = (const float*)d_in[6];
    const float* sigma  = (const float*)d_in[7];
    float* dout = (float*)d_out;

    smn_k0_ssf<<<1, 256>>>(ssf, sigma, dout);
    smn_k1_tc<<<dim3(4, NN / 16), 256>>>(x, W_pre, b_pre, att);
    smn_k2_post<<<NN / 32, 256>>>(W_post, b_post, dout);
    smn_k3_final<<<NN / 64, 256>>>(dout);
}

// round 4
// speedup vs baseline: 2.8090x; 1.2539x over previous
#include <cuda_runtime.h>
#include <math.h>
#include <stdint.h>

#define NN      32768
#define NHOPS   6
#define NFEAT_  512
#define NSSF_   256
#define NCLASS_ 40
#define NEG_    0.2f
#define COS_EPS_ 1e-6f

// output layout (flattened tuple, element offsets)
#define OUT_OFF   0
#define SSFN_OFF  (NN*NCLASS_)                    // 1310720
#define Z_OFF     (SSFN_OFF + NSSF_*NCLASS_)      // 1320960
#define LOSS_OFF  (Z_OFF + NN*NSSF_)              // 9709568
#define SIGMA_OFF (LOSS_OFF + NN*NCLASS_)         // 11020288

// scratch (static device globals — no runtime allocation)
__device__ float g_z1[(long)NN * 512];
__device__ float g_zsq[NN];
__device__ float g_zn[NN];
__device__ float g_csq[NCLASS_];
__device__ float g_cn[NCLASS_];

// ---------------------------------------------------------------------------
// helpers: tf32 convert (round-to-nearest) + m16n8k8 tf32 mma
// ---------------------------------------------------------------------------
__device__ __forceinline__ uint32_t f2tf(float x) {
    uint32_t y;
    asm("cvt.rna.tf32.f32 %0, %1;" : "=r"(y) : "f"(x));
    return y;
}
__device__ __forceinline__ void mma8(float c[4], const uint32_t a[4],
                                     const uint32_t b[2]) {
    asm volatile(
        "mma.sync.aligned.m16n8k8.row.col.f32.tf32.tf32.f32 "
        "{%0,%1,%2,%3}, {%4,%5,%6,%7}, {%8,%9}, {%0,%1,%2,%3};\n"
        : "+f"(c[0]), "+f"(c[1]), "+f"(c[2]), "+f"(c[3])
        : "r"(a[0]), "r"(a[1]), "r"(a[2]), "r"(a[3]), "r"(b[0]), "r"(b[1]));
}

// ---------------------------------------------------------------------------
// K0: exact sparsify threshold (5121-st smallest of |ssf|), ssf_norm,
// per-class column norms, sigma copy. One block.
// ---------------------------------------------------------------------------
__global__ void __launch_bounds__(256) smn_k0_ssf(
    const float* __restrict__ ssf, const float* __restrict__ sigma,
    float* __restrict__ dout)
{
    __shared__ float fbuf[NSSF_ * NCLASS_];
    __shared__ int   cnt_s[256];
    unsigned* keys = reinterpret_cast<unsigned*>(fbuf);
    const int tid = threadIdx.x;

    for (int i = tid; i < NSSF_ * NCLASS_; i += 256)
        keys[i] = __float_as_uint(fabsf(ssf[i]));
    __syncthreads();

    unsigned lo = 0u, hi = 0x7f800000u;
    while (lo < hi) {
        unsigned mid = (lo + hi) >> 1;
        int c = 0;
        for (int i = tid; i < NSSF_ * NCLASS_; i += 256) c += (keys[i] <= mid);
        cnt_s[tid] = c;
        __syncthreads();
        for (int s = 128; s > 0; s >>= 1) {
            if (tid < s) cnt_s[tid] += cnt_s[tid + s];
            __syncthreads();
        }
        int total = cnt_s[0];
        __syncthreads();
        if (total >= 5121) hi = mid; else lo = mid + 1;
    }
    const float thr = __uint_as_float(lo);

    float row[NCLASS_];
    float rs = 0.f;
    const float* srow = ssf + tid * NCLASS_;
#pragma unroll
    for (int j = 0; j < NCLASS_; j++) {
        float v = srow[j];
        v = (fabsf(v) >= thr) ? v : 0.f;
        row[j] = v;
        rs += fabsf(v);
    }
    const float inv = 1.f / fmaxf(rs, 1e-12f);
#pragma unroll
    for (int j = 0; j < NCLASS_; j++) {
        float v = row[j] * inv;
        dout[SSFN_OFF + tid * NCLASS_ + j] = v;
        fbuf[tid * NCLASS_ + j] = v;
    }
    __syncthreads();

    if (tid < NCLASS_) {
        float c2 = 0.f;
        for (int i = 0; i < NSSF_; i++) {
            float v = fbuf[i * NCLASS_ + tid];
            c2 += v * v;
        }
        g_csq[tid] = c2;
        g_cn[tid]  = fmaxf(sqrtf(c2), COS_EPS_);
    }
    if (tid < 2) dout[SIGMA_OFF + tid] = sigma[tid];
}

// ---------------------------------------------------------------------------
// K1 (tf32 mma, double-buffered): h = lrelu(x @ W_pre^T + b) -> hop softmax.
// Block: 96 rows (16 nodes) x 128 cols (2 heads), k pipelined in 32-chunks
// with register prefetch. Warp tile 48x32, m16n8k8 tf32.
// Dynamic smem: atts[768] | As[2][96][36] u32 | Bs[2][128][36] u32 = 67584 B.
// ---------------------------------------------------------------------------
__global__ void __launch_bounds__(256) smn_k1_tc(
    const float* __restrict__ x, const float* __restrict__ Wp,
    const float* __restrict__ bp, const float* __restrict__ att)
{
    extern __shared__ uint32_t dynsmem[];
    float*    atts = (float*)dynsmem;         // 768
    uint32_t* As   = dynsmem + 768;           // 2 * 96*36
    uint32_t* Bs   = As + 2 * 96 * 36;        // 2 * 128*36

    const int tid  = threadIdx.x;
    const int lane = tid & 31, warp = tid >> 5;
    const int warpM = warp >> 2, warpN = warp & 3;
    const int g = lane >> 2, t = lane & 3;
    const int node0 = blockIdx.y * 16;
    const int col0  = blockIdx.x * 128;
    const long row0 = (long)node0 * NHOPS;

    for (int i = tid; i < 768; i += 256)
        atts[i] = att[2 * blockIdx.x * 384 + i];

    // staging register indices (fixed per thread)
    const int ar[3] = { (tid + 0)   >> 3, (tid + 256) >> 3, (tid + 512) >> 3 };
    const int ac    = (tid & 7) * 4;
    float4 a_reg[3], b_reg[4];

    float acc[3][4][4];
#pragma unroll
    for (int mf = 0; mf < 3; mf++)
#pragma unroll
        for (int nf = 0; nf < 4; nf++)
#pragma unroll
            for (int v = 0; v < 4; v++) acc[mf][nf][v] = 0.f;

    // prologue: load + stage chunk 0
#pragma unroll
    for (int i = 0; i < 3; i++)
        a_reg[i] = *(const float4*)(x + (row0 + ar[i]) * NFEAT_ + ac);
#pragma unroll
    for (int i = 0; i < 4; i++) {
        int n = (tid + i * 256) >> 3;
        b_reg[i] = *(const float4*)(Wp + (long)(col0 + n) * NFEAT_ + ac);
    }
#pragma unroll
    for (int i = 0; i < 3; i++) {
        uint32_t* d = As + ar[i] * 36 + ac;
        d[0] = f2tf(a_reg[i].x); d[1] = f2tf(a_reg[i].y);
        d[2] = f2tf(a_reg[i].z); d[3] = f2tf(a_reg[i].w);
    }
#pragma unroll
    for (int i = 0; i < 4; i++) {
        int n = (tid + i * 256) >> 3;
        uint32_t* d = Bs + n * 36 + ac;
        d[0] = f2tf(b_reg[i].x); d[1] = f2tf(b_reg[i].y);
        d[2] = f2tf(b_reg[i].z); d[3] = f2tf(b_reg[i].w);
    }
    __syncthreads();

    for (int it = 0; it < 16; it++) {
        const int buf = it & 1;
        // prefetch next chunk into registers (overlaps with mma below)
        if (it < 15) {
            const int ks = (it + 1) * 32;
#pragma unroll
            for (int i = 0; i < 3; i++)
                a_reg[i] = *(const float4*)(x + (row0 + ar[i]) * NFEAT_ + ks + ac);
#pragma unroll
            for (int i = 0; i < 4; i++) {
                int n = (tid + i * 256) >> 3;
                b_reg[i] = *(const float4*)(Wp + (long)(col0 + n) * NFEAT_ + ks + ac);
            }
        }
        // compute current chunk
        const uint32_t* Ab = As + buf * 3456;
        const uint32_t* Bb = Bs + buf * 4608;
#pragma unroll
        for (int kk = 0; kk < 4; kk++) {
            const int k8 = kk * 8;
            uint32_t af[3][4], bf[4][2];
#pragma unroll
            for (int mf = 0; mf < 3; mf++) {
                const int rb = warpM * 48 + mf * 16;
                af[mf][0] = Ab[(rb + g)     * 36 + k8 + t];
                af[mf][1] = Ab[(rb + g + 8) * 36 + k8 + t];
                af[mf][2] = Ab[(rb + g)     * 36 + k8 + t + 4];
                af[mf][3] = Ab[(rb + g + 8) * 36 + k8 + t + 4];
            }
#pragma unroll
            for (int nf = 0; nf < 4; nf++) {
                const int nb = warpN * 32 + nf * 8;
                bf[nf][0] = Bb[(nb + g) * 36 + k8 + t];
                bf[nf][1] = Bb[(nb + g) * 36 + k8 + t + 4];
            }
#pragma unroll
            for (int mf = 0; mf < 3; mf++)
#pragma unroll
                for (int nf = 0; nf < 4; nf++)
                    mma8(acc[mf][nf], af[mf], bf[nf]);
        }
        // stage prefetched chunk into the other buffer
        if (it < 15) {
            uint32_t* An = As + (buf ^ 1) * 3456;
            uint32_t* Bn = Bs + (buf ^ 1) * 4608;
#pragma unroll
            for (int i = 0; i < 3; i++) {
                uint32_t* d = An + ar[i] * 36 + ac;
                d[0] = f2tf(a_reg[i].x); d[1] = f2tf(a_reg[i].y);
                d[2] = f2tf(a_reg[i].z); d[3] = f2tf(a_reg[i].w);
            }
#pragma unroll
            for (int i = 0; i < 4; i++) {
                int n = (tid + i * 256) >> 3;
                uint32_t* d = Bn + n * 36 + ac;
                d[0] = f2tf(b_reg[i].x); d[1] = f2tf(b_reg[i].y);
                d[2] = f2tf(b_reg[i].z); d[3] = f2tf(b_reg[i].w);
            }
        }
        __syncthreads();
    }

    // epilogue: two 64-col halves through smem (Cs [96][68] reuses As region)
    float* Cs = (float*)As;
#pragma unroll
    for (int half = 0; half < 2; half++) {
        if ((warpN >> 1) == half) {
#pragma unroll
            for (int mf = 0; mf < 3; mf++)
#pragma unroll
                for (int nf = 0; nf < 4; nf++) {
                    const int r  = warpM * 48 + mf * 16 + g;
                    const int cc = (warpN & 1) * 32 + nf * 8 + t * 2;
                    Cs[r * 68 + cc]           = acc[mf][nf][0];
                    Cs[r * 68 + cc + 1]       = acc[mf][nf][1];
                    Cs[(r + 8) * 68 + cc]     = acc[mf][nf][2];
                    Cs[(r + 8) * 68 + cc + 1] = acc[mf][nf][3];
                }
        }
        __syncthreads();
        {
            const int ty = tid >> 4, tx = tid & 15;
            const int node = node0 + ty;
            const int cg = half * 64 + tx * 4;
            float4 b4 = *(const float4*)(bp + col0 + cg);
            float bv[4] = {b4.x, b4.y, b4.z, b4.w};
            float zr[4];
#pragma unroll
            for (int c = 0; c < 4; c++) {
                float h[NHOPS], am[NHOPS], s[NHOPS];
#pragma unroll
                for (int r = 0; r < NHOPS; r++) {
                    float v = Cs[(ty * 6 + r) * 68 + tx * 4 + c] + bv[c];
                    v = v > 0.f ? v : NEG_ * v;
                    h[r]  = v;
                    am[r] = v * atts[half * 384 + r * 64 + tx * 4 + c];
                }
                float m = -1e30f;
#pragma unroll
                for (int r = 0; r < NHOPS; r++) {
                    float u = am[0] + am[r];
                    u = u > 0.f ? u : NEG_ * u;
                    s[r] = u;
                    m = fmaxf(m, u);
                }
                float den = 0.f, num = 0.f;
#pragma unroll
                for (int r = 0; r < NHOPS; r++) {
                    float w = expf(s[r] - m);
                    den += w;
                    num += h[r] * w;
                }
                zr[c] = num / den;
            }
            *(float4*)&g_z1[(long)node * 512 + col0 + cg] =
                make_float4(zr[0], zr[1], zr[2], zr[3]);
        }
        __syncthreads();
    }
}

// ---------------------------------------------------------------------------
// K2 (tf32 mma, double-buffered): z = lrelu(z1 @ W_post^T + b) [N,256],
// plus per-row sum-of-squares + norm. Block 128 rows x 256 cols, 512 threads,
// warp tile 32x64. Dynamic smem: As[2][128][36] | Bs[2][256][36] = 110592 B.
// ---------------------------------------------------------------------------
__global__ void __launch_bounds__(512) smn_k2_tc(
    const float* __restrict__ Wq, const float* __restrict__ bq,
    float* __restrict__ dout)
{
    extern __shared__ uint32_t dynsmem[];
    uint32_t* As = dynsmem;                   // 2 * 128*36
    uint32_t* Bs = As + 2 * 128 * 36;         // 2 * 256*36
    __shared__ float bias_s[256];

    const int tid  = threadIdx.x;
    const int lane = tid & 31, warp = tid >> 5;
    const int warpM = warp >> 2, warpN = warp & 3;
    const int g = lane >> 2, t = lane & 3;
    const long row0 = (long)blockIdx.x * 128;

    if (tid < 256) bias_s[tid] = bq[tid];

    const int ar[2] = { (tid + 0) >> 3, (tid + 512) >> 3 };
    const int ac    = (tid & 7) * 4;
    float4 a_reg[2], b_reg[4];

    float acc[2][8][4];
#pragma unroll
    for (int mf = 0; mf < 2; mf++)
#pragma unroll
        for (int nf = 0; nf < 8; nf++)
#pragma unroll
            for (int v = 0; v < 4; v++) acc[mf][nf][v] = 0.f;

#pragma unroll
    for (int i = 0; i < 2; i++)
        a_reg[i] = *(const float4*)(g_z1 + (row0 + ar[i]) * 512 + ac);
#pragma unroll
    for (int i = 0; i < 4; i++) {
        int n = (tid + i * 512) >> 3;
        b_reg[i] = *(const float4*)(Wq + (long)n * 512 + ac);
    }
#pragma unroll
    for (int i = 0; i < 2; i++) {
        uint32_t* d = As + ar[i] * 36 + ac;
        d[0] = f2tf(a_reg[i].x); d[1] = f2tf(a_reg[i].y);
        d[2] = f2tf(a_reg[i].z); d[3] = f2tf(a_reg[i].w);
    }
#pragma unroll
    for (int i = 0; i < 4; i++) {
        int n = (tid + i * 512) >> 3;
        uint32_t* d = Bs + n * 36 + ac;
        d[0] = f2tf(b_reg[i].x); d[1] = f2tf(b_reg[i].y);
        d[2] = f2tf(b_reg[i].z); d[3] = f2tf(b_reg[i].w);
    }
    __syncthreads();

    for (int it = 0; it < 16; it++) {
        const int buf = it & 1;
        if (it < 15) {
            const int ks = (it + 1) * 32;
#pragma unroll
            for (int i = 0; i < 2; i++)
                a_reg[i] = *(const float4*)(g_z1 + (row0 + ar[i]) * 512 + ks + ac);
#pragma unroll
            for (int i = 0; i < 4; i++) {
                int n = (tid + i * 512) >> 3;
                b_reg[i] = *(const float4*)(Wq + (long)n * 512 + ks + ac);
            }
        }
        const uint32_t* Ab = As + buf * 4608;
        const uint32_t* Bb = Bs + buf * 9216;
#pragma unroll
        for (int kk = 0; kk < 4; kk++) {
            const int k8 = kk * 8;
            uint32_t af[2][4], bf[8][2];
#pragma unroll
            for (int mf = 0; mf < 2; mf++) {
                const int rb = warpM * 32 + mf * 16;
                af[mf][0] = Ab[(rb + g)     * 36 + k8 + t];
                af[mf][1] = Ab[(rb + g + 8) * 36 + k8 + t];
                af[mf][2] = Ab[(rb + g)     * 36 + k8 + t + 4];
                af[mf][3] = Ab[(rb + g + 8) * 36 + k8 + t + 4];
            }
#pragma unroll
            for (int nf = 0; nf < 8; nf++) {
                const int nb = warpN * 64 + nf * 8;
                bf[nf][0] = Bb[(nb + g) * 36 + k8 + t];
                bf[nf][1] = Bb[(nb + g) * 36 + k8 + t + 4];
            }
#pragma unroll
            for (int mf = 0; mf < 2; mf++)
#pragma unroll
                for (int nf = 0; nf < 8; nf++)
                    mma8(acc[mf][nf], af[mf], bf[nf]);
        }
        if (it < 15) {
            uint32_t* An = As + (buf ^ 1) * 4608;
            uint32_t* Bn = Bs + (buf ^ 1) * 9216;
#pragma unroll
            for (int i = 0; i < 2; i++) {
                uint32_t* d = An + ar[i] * 36 + ac;
                d[0] = f2tf(a_reg[i].x); d[1] = f2tf(a_reg[i].y);
                d[2] = f2tf(a_reg[i].z); d[3] = f2tf(a_reg[i].w);
            }
#pragma unroll
            for (int i = 0; i < 4; i++) {
                int n = (tid + i * 512) >> 3;
                uint32_t* d = Bn + n * 36 + ac;
                d[0] = f2tf(b_reg[i].x); d[1] = f2tf(b_reg[i].y);
                d[2] = f2tf(b_reg[i].z); d[3] = f2tf(b_reg[i].w);
            }
        }
        __syncthreads();
    }

    // epilogue: bias + lrelu + store z + per-row sum of squares
    float* part = (float*)As;     // [128][4]
    float zp[4] = {0.f, 0.f, 0.f, 0.f};
#pragma unroll
    for (int mf = 0; mf < 2; mf++) {
#pragma unroll
        for (int nf = 0; nf < 8; nf++) {
            const int rl  = warpM * 32 + mf * 16 + g;
            const int col = warpN * 64 + nf * 8 + t * 2;
            float v0 = acc[mf][nf][0] + bias_s[col];
            float v1 = acc[mf][nf][1] + bias_s[col + 1];
            float v2 = acc[mf][nf][2] + bias_s[col];
            float v3 = acc[mf][nf][3] + bias_s[col + 1];
            v0 = v0 > 0.f ? v0 : NEG_ * v0;
            v1 = v1 > 0.f ? v1 : NEG_ * v1;
            v2 = v2 > 0.f ? v2 : NEG_ * v2;
            v3 = v3 > 0.f ? v3 : NEG_ * v3;
            *(float2*)&dout[Z_OFF + (row0 + rl) * 256 + col] =
                make_float2(v0, v1);
            *(float2*)&dout[Z_OFF + (row0 + rl + 8) * 256 + col] =
                make_float2(v2, v3);
            zp[mf * 2]     += v0 * v0 + v1 * v1;
            zp[mf * 2 + 1] += v2 * v2 + v3 * v3;
        }
    }
#pragma unroll
    for (int j = 0; j < 4; j++) {
        zp[j] += __shfl_xor_sync(0xffffffffu, zp[j], 1);
        zp[j] += __shfl_xor_sync(0xffffffffu, zp[j], 2);
    }
    if (t == 0) {
#pragma unroll
        for (int j = 0; j < 4; j++) {
            const int rl = warpM * 32 + (j >> 1) * 16 + g + (j & 1) * 8;
            part[rl * 4 + warpN] = zp[j];
        }
    }
    __syncthreads();
    if (tid < 128) {
        float s = part[tid * 4] + part[tid * 4 + 1]
                + part[tid * 4 + 2] + part[tid * 4 + 3];
        g_zsq[row0 + tid] = s;
        g_zn[row0 + tid]  = fmaxf(sqrtf(s), COS_EPS_);
    }
}

// ---------------------------------------------------------------------------
// K3: out = z @ ssf_norm; spatial_dist / spatial_sim; two row log-softmaxes.
// ---------------------------------------------------------------------------
__global__ void __launch_bounds__(256) smn_k3_final(float* __restrict__ dout)
{
    __shared__ float ssfn_s[NSSF_ * NCLASS_];
    const float* ssfn_g = dout + SSFN_OFF;
    const int tid = threadIdx.x;
    for (int i = tid; i < NSSF_ * NCLASS_; i += 256) ssfn_s[i] = ssfn_g[i];
    __syncthreads();

    const int warp = tid >> 5, lane = tid & 31;
    const bool has2 = lane < 8;
    const int j1 = lane, j2 = 32 + lane;
    const float csq1 = g_csq[j1], cn1 = g_cn[j1];
    const float csq2 = has2 ? g_csq[j2] : 0.f;
    const float cn2  = has2 ? g_cn[j2]  : 1.f;
    const float* zbase = dout + Z_OFF;

    for (int it = 0; it < 8; it++) {
        const long row = (long)blockIdx.x * 64 + warp * 8 + it;
        const float* zr = zbase + row * 256 + lane * 8;
        float4 za = *(const float4*)zr;
        float4 zb = *(const float4*)(zr + 4);
        float zreg[8] = {za.x, za.y, za.z, za.w, zb.x, zb.y, zb.z, zb.w};

        float acc1 = 0.f, acc2 = 0.f;
#pragma unroll
        for (int m = 0; m < 8; m++) {
#pragma unroll 8
            for (int src = 0; src < 32; src++) {
                float zv = __shfl_sync(0xffffffffu, zreg[m], src);
                int i = src * 8 + m;
                acc1 += zv * ssfn_s[i * NCLASS_ + j1];
                if (has2) acc2 += zv * ssfn_s[i * NCLASS_ + j2];
            }
        }

        const float zsq = g_zsq[row];
        const float zn  = g_zn[row];
        float d1 = -sqrtf(fmaxf(zsq + csq1 - 2.f * acc1, 0.f));
        float s1 = acc1 / (zn * cn1);
        float d2 = has2 ? -sqrtf(fmaxf(zsq + csq2 - 2.f * acc2, 0.f)) : -1e30f;
        float s2 = has2 ? acc2 / (zn * cn2) : -1e30f;

        float md = fmaxf(d1, d2);
        float ms = fmaxf(s1, s2);
#pragma unroll
        for (int o = 16; o > 0; o >>= 1) {
            md = fmaxf(md, __shfl_xor_sync(0xffffffffu, md, o));
            ms = fmaxf(ms, __shfl_xor_sync(0xffffffffu, ms, o));
        }
        float ed = expf(d1 - md) + (has2 ? expf(d2 - md) : 0.f);
        float es = expf(s1 - ms) + (has2 ? expf(s2 - ms) : 0.f);
#pragma unroll
        for (int o = 16; o > 0; o >>= 1) {
            ed += __shfl_xor_sync(0xffffffffu, ed, o);
            es += __shfl_xor_sync(0xffffffffu, es, o);
        }
        const float lse_d = md + logf(ed);
        const float lse_s = ms + logf(es);

        dout[OUT_OFF  + row * NCLASS_ + j1] = acc1;
        dout[LOSS_OFF + row * NCLASS_ + j1] =
            0.5f * ((d1 - lse_d) + (s1 - lse_s));
        if (has2) {
            dout[OUT_OFF  + row * NCLASS_ + j2] = acc2;
            dout[LOSS_OFF + row * NCLASS_ + j2] =
                0.5f * ((d2 - lse_d) + (s2 - lse_s));
        }
    }
}

// ---------------------------------------------------------------------------
extern "C" void kernel_launch(void* const* d_in, const int* in_sizes, int n_in,
                              void* d_out, int out_size)
{
    const float* x      = (const float*)d_in[0];
    const float* W_pre  = (const float*)d_in[1];
    const float* b_pre  = (const float*)d_in[2];
    const float* att    = (const float*)d_in[3];
    const float* W_post = (const float*)d_in[4];
    const float* b_post = (const float*)d_in[5];
    const float* ssf    = (const float*)d_in[6];
    const float* sigma  = (const float*)d_in[7];
    float* dout = (float*)d_out;

    const int K1_SMEM = (768 + 2 * 96 * 36 + 2 * 128 * 36) * 4;   // 67584
    const int K2_SMEM = (2 * 128 * 36 + 2 * 256 * 36) * 4;        // 110592
    cudaFuncSetAttribute(smn_k1_tc,
                         cudaFuncAttributeMaxDynamicSharedMemorySize, K1_SMEM);
    cudaFuncSetAttribute(smn_k2_tc,
                         cudaFuncAttributeMaxDynamicSharedMemorySize, K2_SMEM);

    smn_k0_ssf<<<1, 256>>>(ssf, sigma, dout);
    smn_k1_tc<<<dim3(4, NN / 16), 256, K1_SMEM>>>(x, W_pre, b_pre, att);
    smn_k2_tc<<<NN / 128, 512, K2_SMEM>>>(W_post, b_post, dout);
    smn_k3_final<<<NN / 64, 256>>>(dout);
}